// round 13
// baseline (speedup 1.0000x reference)
#include <cuda_runtime.h>
#include <cuda_fp16.h>
#include <cstdint>
#include <cstddef>

#define NE 16
#define HD 2048
#define ID 1536
#define TT 32768

// ---------------- device scratch (allocation-free rule) -------------------------
__device__ __half g_xh[(size_t)TT * HD];                  // x fp16          (128MB)
__device__ __half g_gate[(size_t)TT * ID];                // gate proj fp16  ( 96MB)
__device__ __half g_hid[(size_t)TT * ID];                 // silu(g)*up fp16 ( 96MB)

// ---------------- helpers -------------------------------------------------------
__device__ __forceinline__ uint32_t smem_u32(const void* p) {
    uint32_t a;
    asm("{ .reg .u64 t; cvta.to.shared.u64 t, %1; cvt.u32.u64 %0, t; }" : "=r"(a) : "l"(p));
    return a;
}
__device__ __forceinline__ void cp16(uint32_t dst, const void* src) {
    asm volatile("cp.async.cg.shared.global [%0], [%1], 16;" :: "r"(dst), "l"(src));
}
__device__ __forceinline__ void sts128(uint32_t addr, uint32_t x, uint32_t y,
                                       uint32_t z, uint32_t w) {
    asm volatile("st.shared.v4.b32 [%0], {%1,%2,%3,%4};"
                 :: "r"(addr), "r"(x), "r"(y), "r"(z), "r"(w));
}
__device__ __forceinline__ void ldsm4(uint32_t& r0, uint32_t& r1, uint32_t& r2,
                                      uint32_t& r3, uint32_t a) {
    asm volatile("ldmatrix.sync.aligned.m8n8.x4.shared.b16 {%0,%1,%2,%3}, [%4];"
                 : "=r"(r0), "=r"(r1), "=r"(r2), "=r"(r3) : "r"(a));
}
__device__ __forceinline__ void ldsm4t(uint32_t& r0, uint32_t& r1, uint32_t& r2,
                                       uint32_t& r3, uint32_t a) {
    asm volatile("ldmatrix.sync.aligned.m8n8.x4.trans.shared.b16 {%0,%1,%2,%3}, [%4];"
                 : "=r"(r0), "=r"(r1), "=r"(r2), "=r"(r3) : "r"(a));
}
__device__ __forceinline__ void mma16816(float* c, uint32_t a0, uint32_t a1, uint32_t a2,
                                         uint32_t a3, uint32_t b0, uint32_t b1) {
    asm volatile(
        "mma.sync.aligned.m16n8k16.row.col.f32.f16.f16.f32 "
        "{%0,%1,%2,%3}, {%4,%5,%6,%7}, {%8,%9}, {%0,%1,%2,%3};"
        : "+f"(c[0]), "+f"(c[1]), "+f"(c[2]), "+f"(c[3])
        : "r"(a0), "r"(a1), "r"(a2), "r"(a3), "r"(b0), "r"(b1));
}
__device__ __forceinline__ uint32_t pk(float a, float b) {
    __half2 h = __floats2half2_rn(a, b);
    return *reinterpret_cast<uint32_t*>(&h);
}
__device__ __forceinline__ float silu_f(float x) { return x / (1.0f + __expf(-x)); }

// ---------------- fp32 -> fp16 converter (x only; weights read raw) -------------
__global__ void cvt_f2h(const float4* __restrict__ src, __half* __restrict__ dst,
                        int n4) {
    int i = blockIdx.x * blockDim.x + threadIdx.x;
    if (i < n4) {
        float4 v = src[i];
        uint2 o;
        o.x = pk(v.x, v.y);
        o.y = pk(v.z, v.w);
        *reinterpret_cast<uint2*>(dst + (size_t)i * 4) = o;
    }
}

// ---------------- grouped GEMM (mma.sync fp16, fp32 accum) ----------------------
// R12 core: CTA tile 128x128, K-chunk 64, 256 threads (8 warps, 2x4 grid of
// 64x32 warp tiles), 2 CTAs/SM, 3-stage pipeline.
// NEW: B (weights) consumed DIRECTLY as fp32 from the input tensors:
//   per ks-step: STS fp16 of the previous fp32 LDG pair, then issue the next
//   LDG.128 pair -> no weight-conversion prep pass, identical fp16 bits.
// A: fp16 (converted x / gate-stage outputs) via cp.async, interleaved 1/ks.
// MODE 0: write fp16 raw (gate)
// MODE 1: write fp16 silu(G)*acc reading G  (up, fused SiLU)
// MODE 2: write fp32                        (down)
static constexpr int STG_A = 128 * 64 * 2;     // 16KB
static constexpr int STG_B = 64 * 128 * 2;     // 16KB
static constexpr int STG = STG_A + STG_B;      // 32KB
static constexpr int SMEM_DYN = 3 * STG + 128; // ~96KB

template <int KDIM, int NDIM, int MODE>
__global__ void __launch_bounds__(256, 2)
gemm_moe(const __half* __restrict__ Ag, const float* __restrict__ Ball,
         void* __restrict__ Cv, const __half* __restrict__ Gv,
         const int* __restrict__ gs) {
    extern __shared__ char dsm[];
    __shared__ int s_cum[NE];

    const int tid = threadIdx.x;
    if (tid == 0) {
        int c = 0;
#pragma unroll
        for (int k = 0; k < NE; ++k) { s_cum[k] = c; c += gs[k]; }
    }
    __syncthreads();

    const int m0 = blockIdx.y * 128;
    const int n0 = blockIdx.x * 128;
    int e = 0;
#pragma unroll
    for (int k = 1; k < NE; ++k) e += (s_cum[k] <= m0) ? 1 : 0;

    const float* Bg = Ball + (size_t)e * KDIM * NDIM + n0;
    const __half* Ap = Ag + (size_t)m0 * KDIM;

    const uint32_t base = (smem_u32(dsm) + 127u) & ~127u;
    const int lane = tid & 31, wid = tid >> 5;
    const int wm = wid >> 2, wn = wid & 3;

    // ---- per-thread load geometry ----
    const int rA = tid >> 3, qA = tid & 7;
    const uint32_t oA0 = rA * 128 + ((qA ^ (rA & 7)) << 4);
    const __half* gAp = Ap + (size_t)rA * KDIM + qA * 8;
    // B fp32: thread covers rows rB+16*it, 8-float group cB (32B).
    const int rB = tid >> 4, cB = tid & 15;
    const uint32_t oB0 = rB * 256 + ((cB ^ (rB & 7)) << 4);   // fp16 dst offset
    const float* gBp = Bg + (size_t)rB * NDIM + cB * 8;

    auto load_full = [&](int slot, int ch) {     // prologue loader
        const uint32_t dA = base + slot * STG + oA0;
        const uint32_t dB = base + slot * STG + STG_A + oB0;
        const __half* sa = gAp + ch * 64;
        const float* sb = gBp + (size_t)(ch * 64) * NDIM;
#pragma unroll
        for (int it = 0; it < 4; ++it)
            cp16(dA + it * 4096, sa + (size_t)(it * 32) * KDIM);
#pragma unroll 1
        for (int it = 0; it < 4; ++it) {         // unroll 1: cap reg pressure
            const float* p = sb + (size_t)(it * 16) * NDIM;
            float4 f0 = *(const float4*)p;
            float4 f1 = *(const float4*)(p + 4);
            sts128(dB + it * 4096, pk(f0.x, f0.y), pk(f0.z, f0.w),
                   pk(f1.x, f1.y), pk(f1.z, f1.w));
        }
        asm volatile("cp.async.commit_group;" ::: "memory");
    };

    float acc[4][4][4];
#pragma unroll
    for (int a = 0; a < 4; ++a)
#pragma unroll
        for (int b = 0; b < 4; ++b)
#pragma unroll
            for (int c = 0; c < 4; ++c) acc[a][b][c] = 0.f;

    // compute chunk in slot, loading chunk 'ch' (fp32 B + cp.async A) into 'dst'
    auto step = [&](int slot, int dst, int ch, bool doload) {
        const uint32_t Ab = base + slot * STG;
        const uint32_t Bb = Ab + STG_A;
        const uint32_t dA = base + dst * STG + oA0;
        const uint32_t dB = base + dst * STG + STG_A + oB0;
        const __half* sa = gAp + ch * 64;
        const float* sb = gBp + (size_t)(ch * 64) * NDIM;
        const int sub = lane >> 3, lr = lane & 7;
        float4 fa, fb;                           // in-flight fp32 B (8 regs)
#pragma unroll
        for (int ks = 0; ks < 4; ++ks) {
            uint32_t bfr[8];
#pragma unroll
            for (int np = 0; np < 2; ++np) {
                int krow = ks * 16 + (sub & 1) * 8 + lr;
                int ng = wn * 4 + np * 2 + (sub >> 1);
                uint32_t addr = Bb + krow * 256 + ((ng ^ (krow & 7)) << 4);
                ldsm4t(bfr[np * 4 + 0], bfr[np * 4 + 1], bfr[np * 4 + 2],
                       bfr[np * 4 + 3], addr);
            }
            if (doload) {
                if (ks > 0)                       // store B loaded last ks-step
                    sts128(dB + (ks - 1) * 4096, pk(fa.x, fa.y), pk(fa.z, fa.w),
                           pk(fb.x, fb.y), pk(fb.z, fb.w));
                const float* p = sb + (size_t)(ks * 16) * NDIM;
                fa = *(const float4*)p;
                fb = *(const float4*)(p + 4);
                cp16(dA + ks * 4096, sa + (size_t)(ks * 32) * KDIM);
            }
#pragma unroll
            for (int mb = 0; mb < 4; ++mb) {
                int row = wm * 64 + mb * 16 + (sub & 1) * 8 + lr;
                int q = ks * 2 + (sub >> 1);
                uint32_t addr = Ab + row * 128 + ((q ^ (row & 7)) << 4);
                uint32_t a0, a1, a2, a3;
                ldsm4(a0, a1, a2, a3, addr);
#pragma unroll
                for (int np = 0; np < 2; ++np) {
                    mma16816(acc[mb][np * 2 + 0], a0, a1, a2, a3,
                             bfr[np * 4 + 0], bfr[np * 4 + 1]);
                    mma16816(acc[mb][np * 2 + 1], a0, a1, a2, a3,
                             bfr[np * 4 + 2], bfr[np * 4 + 3]);
                }
            }
        }
        if (doload) {
            sts128(dB + 3 * 4096, pk(fa.x, fa.y), pk(fa.z, fa.w),
                   pk(fb.x, fb.y), pk(fb.z, fb.w));
            asm volatile("cp.async.commit_group;" ::: "memory");
        }
    };

    const int nch = KDIM / 64;

    load_full(0, 0);
    load_full(1, 1);

#pragma unroll 1
    for (int i = 0; i < nch; ++i) {
        if (i + 1 < nch) asm volatile("cp.async.wait_group 1;" ::: "memory");
        else             asm volatile("cp.async.wait_group 0;" ::: "memory");
        __syncthreads();
        const bool dl = (i + 2 < nch);
        step(i % 3, (i + 2) % 3, dl ? (i + 2) : 0, dl);
    }

    // ---- epilogue ----
    const int r0 = m0 + wm * 64 + (lane >> 2);
    const int c0 = n0 + wn * 32 + (lane & 3) * 2;

#pragma unroll
    for (int mb = 0; mb < 4; ++mb) {
#pragma unroll
        for (int nb = 0; nb < 4; ++nb) {
            const int rr = r0 + mb * 16;
            const int cc = c0 + nb * 8;
            const size_t o0 = (size_t)rr * NDIM + cc;
            const size_t o1 = (size_t)(rr + 8) * NDIM + cc;
            float* a = acc[mb][nb];
            if (MODE == 0) {
                __half* C = (__half*)Cv;
                *(uint32_t*)(C + o0) = pk(a[0], a[1]);
                *(uint32_t*)(C + o1) = pk(a[2], a[3]);
            } else if (MODE == 1) {
                __half* C = (__half*)Cv;
                __half2 g0 = *(const __half2*)(Gv + o0);
                __half2 g1 = *(const __half2*)(Gv + o1);
                float2 f0 = __half22float2(g0);
                float2 f1 = __half22float2(g1);
                *(uint32_t*)(C + o0) = pk(silu_f(f0.x) * a[0], silu_f(f0.y) * a[1]);
                *(uint32_t*)(C + o1) = pk(silu_f(f1.x) * a[2], silu_f(f1.y) * a[3]);
            } else {
                float* C = (float*)Cv;
                *(float2*)(C + o0) = make_float2(a[0], a[1]);
                *(float2*)(C + o1) = make_float2(a[2], a[3]);
            }
        }
    }
}

// ---------------- host launcher -------------------------------------------------
extern "C" void kernel_launch(void* const* d_in, const int* in_sizes, int n_in,
                              void* d_out, int out_size) {
    const float* x  = (const float*)d_in[0];
    const float* gw = (const float*)d_in[1];
    const float* uw = (const float*)d_in[2];
    const float* dw = (const float*)d_in[3];
    const int*   gs = (const int*)d_in[4];
    float* out = (float*)d_out;

    // Resolve REAL device addresses of __device__ scratch (host shadow trap).
    void *p_xh = nullptr, *p_gate = nullptr, *p_hid = nullptr;
    cudaGetSymbolAddress(&p_xh, g_xh);
    cudaGetSymbolAddress(&p_gate, g_gate);
    cudaGetSymbolAddress(&p_hid, g_hid);
    __half* xh   = (__half*)p_xh;
    __half* gate = (__half*)p_gate;
    __half* hid  = (__half*)p_hid;

    cudaFuncSetAttribute(gemm_moe<HD, ID, 0>,
                         cudaFuncAttributeMaxDynamicSharedMemorySize, SMEM_DYN);
    cudaFuncSetAttribute(gemm_moe<HD, ID, 1>,
                         cudaFuncAttributeMaxDynamicSharedMemorySize, SMEM_DYN);
    cudaFuncSetAttribute(gemm_moe<ID, HD, 2>,
                         cudaFuncAttributeMaxDynamicSharedMemorySize, SMEM_DYN);

    // fp32 -> fp16 conversion: x only (weights consumed raw fp32 by the GEMMs)
    const int nx4 = (TT * HD) / 4;
    cvt_f2h<<<(nx4 + 255) / 256, 256>>>((const float4*)x, xh, nx4);

    // gate = x @ gate_w             -> g_gate (fp16)
    gemm_moe<HD, ID, 0><<<dim3(ID / 128, TT / 128), 256, SMEM_DYN>>>(
        xh, gw, gate, nullptr, gs);
    // hid = silu(gate) * (x @ up_w) -> g_hid (fp16, fused epilogue)
    gemm_moe<HD, ID, 1><<<dim3(ID / 128, TT / 128), 256, SMEM_DYN>>>(
        xh, uw, hid, gate, gs);
    // out = hid @ down_w            -> out (fp32)
    gemm_moe<ID, HD, 2><<<dim3(HD / 128, TT / 128), 256, SMEM_DYN>>>(
        hid, dw, out, nullptr, gs);
}

// round 14
// speedup vs baseline: 1.4138x; 1.4138x over previous
#include <cuda_runtime.h>
#include <cuda_fp16.h>
#include <cstdint>
#include <cstddef>

#define NE 16
#define HD 2048
#define ID 1536
#define TT 32768

// ---------------- device scratch (allocation-free rule) -------------------------
__device__ __half g_xh[(size_t)TT * HD];                  // x fp16          (128MB)
__device__ __half g_gate[(size_t)TT * ID];                // gate proj fp16  ( 96MB)
__device__ __half g_hid[(size_t)TT * ID];                 // silu(g)*up fp16 ( 96MB)
__device__ __half g_wh[(size_t)NE * 3 * HD * ID];         // fp16 weights    (302MB)

// ---------------- helpers -------------------------------------------------------
__device__ __forceinline__ uint32_t smem_u32(const void* p) {
    uint32_t a;
    asm("{ .reg .u64 t; cvta.to.shared.u64 t, %1; cvt.u32.u64 %0, t; }" : "=r"(a) : "l"(p));
    return a;
}
__device__ __forceinline__ void cp16(uint32_t dst, const void* src) {
    asm volatile("cp.async.cg.shared.global [%0], [%1], 16;" :: "r"(dst), "l"(src));
}
__device__ __forceinline__ void ldsm4(uint32_t& r0, uint32_t& r1, uint32_t& r2,
                                      uint32_t& r3, uint32_t a) {
    asm volatile("ldmatrix.sync.aligned.m8n8.x4.shared.b16 {%0,%1,%2,%3}, [%4];"
                 : "=r"(r0), "=r"(r1), "=r"(r2), "=r"(r3) : "r"(a));
}
__device__ __forceinline__ void ldsm4t(uint32_t& r0, uint32_t& r1, uint32_t& r2,
                                       uint32_t& r3, uint32_t a) {
    asm volatile("ldmatrix.sync.aligned.m8n8.x4.trans.shared.b16 {%0,%1,%2,%3}, [%4];"
                 : "=r"(r0), "=r"(r1), "=r"(r2), "=r"(r3) : "r"(a));
}
__device__ __forceinline__ void mma16816(float* c, uint32_t a0, uint32_t a1, uint32_t a2,
                                         uint32_t a3, uint32_t b0, uint32_t b1) {
    asm volatile(
        "mma.sync.aligned.m16n8k16.row.col.f32.f16.f16.f32 "
        "{%0,%1,%2,%3}, {%4,%5,%6,%7}, {%8,%9}, {%0,%1,%2,%3};"
        : "+f"(c[0]), "+f"(c[1]), "+f"(c[2]), "+f"(c[3])
        : "r"(a0), "r"(a1), "r"(a2), "r"(a3), "r"(b0), "r"(b1));
}
__device__ __forceinline__ uint32_t pk(float a, float b) {
    __half2 h = __floats2half2_rn(a, b);
    return *reinterpret_cast<uint32_t*>(&h);
}
__device__ __forceinline__ float silu_f(float x) { return x / (1.0f + __expf(-x)); }

// ---------------- fp32 -> fp16 conversion (x + gate_w, one launch) ---------------
// z=0: x (n4x float4s) -> g_xh ;  z=1: gate_w (n4w) -> wh_g
__global__ void cvt_xgw(const float4* __restrict__ x, const float4* __restrict__ gw,
                        __half* __restrict__ xd, __half* __restrict__ gd,
                        int n4x, int n4w) {
    int i = blockIdx.x * blockDim.x + threadIdx.x;
    const float4* src;
    __half* dst;
    int n;
    if (blockIdx.z == 0) { src = x;  dst = xd; n = n4x; }
    else                 { src = gw; dst = gd; n = n4w; }
    if (i < n) {
        float4 v = src[i];
        uint2 o;
        o.x = pk(v.x, v.y);
        o.y = pk(v.z, v.w);
        *reinterpret_cast<uint2*>(dst + (size_t)i * 4) = o;
    }
}

// ---------------- grouped GEMM (R12 core: mma.sync fp16, fp32 accum) -------------
// CTA tile 128x128, K-chunk 64, 256 threads (8 warps, 2x4 grid of 64x32 warp
// tiles), 2 CTAs/SM, 3-stage cp.async pipeline; loads for chunk i+2 interleaved
// into the 4 ks-steps of compute(i).
// MODE 0: write fp16 raw (gate) + SIDEBAND: convert up_w+down_w fp32->fp16
//         (grid-stride after epilogue; hides under idle DRAM + wave tail)
// MODE 1: write fp16 silu(G)*acc reading G  (up, fused SiLU)
// MODE 2: write fp32                        (down)
static constexpr int STG_A = 128 * 64 * 2;     // 16KB
static constexpr int STG_B = 64 * 128 * 2;     // 16KB
static constexpr int STG = STG_A + STG_B;      // 32KB
static constexpr int SMEM_DYN = 3 * STG + 128; // ~96KB

template <int KDIM, int NDIM, int MODE>
__global__ void __launch_bounds__(256, 2)
gemm_moe(const __half* __restrict__ Ag, const __half* __restrict__ Ball,
         void* __restrict__ Cv, const __half* __restrict__ Gv,
         const int* __restrict__ gs,
         const float4* __restrict__ wsrc0, const float4* __restrict__ wsrc1,
         uint2* __restrict__ wdst0, uint2* __restrict__ wdst1, int n4w) {
    extern __shared__ char dsm[];
    __shared__ int s_cum[NE];

    const int tid = threadIdx.x;
    if (tid == 0) {
        int c = 0;
#pragma unroll
        for (int k = 0; k < NE; ++k) { s_cum[k] = c; c += gs[k]; }
    }
    __syncthreads();

    const int m0 = blockIdx.y * 128;
    const int n0 = blockIdx.x * 128;
    int e = 0;
#pragma unroll
    for (int k = 1; k < NE; ++k) e += (s_cum[k] <= m0) ? 1 : 0;

    const __half* Bg = Ball + (size_t)e * KDIM * NDIM + n0;
    const __half* Ap = Ag + (size_t)m0 * KDIM;

    const uint32_t base = (smem_u32(dsm) + 127u) & ~127u;
    const int lane = tid & 31, wid = tid >> 5;
    const int wm = wid >> 2, wn = wid & 3;

    // ---- per-thread load geometry (constant for whole kernel) ----
    const int rA = tid >> 3, qA = tid & 7;
    const uint32_t oA0 = rA * 128 + ((qA ^ (rA & 7)) << 4);
    const __half* gAp = Ap + (size_t)rA * KDIM + qA * 8;
    const int rB = tid >> 4, cB = tid & 15;
    const uint32_t oB0 = rB * 256 + ((cB ^ (rB & 7)) << 4);
    const __half* gBp = Bg + (size_t)rB * NDIM + cB * 8;

    auto load_full = [&](int slot, int ch) {
        const uint32_t dA = base + slot * STG + oA0;
        const uint32_t dB = base + slot * STG + STG_A + oB0;
        const __half* sa = gAp + ch * 64;
        const __half* sb = gBp + (size_t)(ch * 64) * NDIM;
#pragma unroll
        for (int it = 0; it < 4; ++it)
            cp16(dA + it * 4096, sa + (size_t)(it * 32) * KDIM);
#pragma unroll
        for (int it = 0; it < 4; ++it)
            cp16(dB + it * 4096, sb + (size_t)(it * 16) * NDIM);
        asm volatile("cp.async.commit_group;" ::: "memory");
    };

    float acc[4][4][4];
#pragma unroll
    for (int a = 0; a < 4; ++a)
#pragma unroll
        for (int b = 0; b < 4; ++b)
#pragma unroll
            for (int c = 0; c < 4; ++c) acc[a][b][c] = 0.f;

    auto step = [&](int slot, int dst, int ch, bool doload) {
        const uint32_t Ab = base + slot * STG;
        const uint32_t Bb = Ab + STG_A;
        const uint32_t dA = base + dst * STG + oA0;
        const uint32_t dB = base + dst * STG + STG_A + oB0;
        const __half* sa = gAp + ch * 64;
        const __half* sb = gBp + (size_t)(ch * 64) * NDIM;
        const int sub = lane >> 3, lr = lane & 7;
#pragma unroll
        for (int ks = 0; ks < 4; ++ks) {
            uint32_t bfr[8];
#pragma unroll
            for (int np = 0; np < 2; ++np) {
                int krow = ks * 16 + (sub & 1) * 8 + lr;
                int ng = wn * 4 + np * 2 + (sub >> 1);
                uint32_t addr = Bb + krow * 256 + ((ng ^ (krow & 7)) << 4);
                ldsm4t(bfr[np * 4 + 0], bfr[np * 4 + 1], bfr[np * 4 + 2],
                       bfr[np * 4 + 3], addr);
            }
            if (doload) {
                cp16(dA + ks * 4096, sa + (size_t)(ks * 32) * KDIM);
                cp16(dB + ks * 4096, sb + (size_t)(ks * 16) * NDIM);
            }
#pragma unroll
            for (int mb = 0; mb < 4; ++mb) {
                int row = wm * 64 + mb * 16 + (sub & 1) * 8 + lr;
                int q = ks * 2 + (sub >> 1);
                uint32_t addr = Ab + row * 128 + ((q ^ (row & 7)) << 4);
                uint32_t a0, a1, a2, a3;
                ldsm4(a0, a1, a2, a3, addr);
#pragma unroll
                for (int np = 0; np < 2; ++np) {
                    mma16816(acc[mb][np * 2 + 0], a0, a1, a2, a3,
                             bfr[np * 4 + 0], bfr[np * 4 + 1]);
                    mma16816(acc[mb][np * 2 + 1], a0, a1, a2, a3,
                             bfr[np * 4 + 2], bfr[np * 4 + 3]);
                }
            }
        }
        if (doload) asm volatile("cp.async.commit_group;" ::: "memory");
    };

    const int nch = KDIM / 64;

    load_full(0, 0);
    load_full(1, 1);

#pragma unroll 1
    for (int i = 0; i < nch; ++i) {
        if (i + 1 < nch) asm volatile("cp.async.wait_group 1;" ::: "memory");
        else             asm volatile("cp.async.wait_group 0;" ::: "memory");
        __syncthreads();
        const bool dl = (i + 2 < nch);
        step(i % 3, (i + 2) % 3, dl ? (i + 2) : 0, dl);
    }

    // ---- epilogue ----
    const int r0 = m0 + wm * 64 + (lane >> 2);
    const int c0 = n0 + wn * 32 + (lane & 3) * 2;

#pragma unroll
    for (int mb = 0; mb < 4; ++mb) {
#pragma unroll
        for (int nb = 0; nb < 4; ++nb) {
            const int rr = r0 + mb * 16;
            const int cc = c0 + nb * 8;
            const size_t o0 = (size_t)rr * NDIM + cc;
            const size_t o1 = (size_t)(rr + 8) * NDIM + cc;
            float* a = acc[mb][nb];
            if (MODE == 0) {
                __half* C = (__half*)Cv;
                *(uint32_t*)(C + o0) = pk(a[0], a[1]);
                *(uint32_t*)(C + o1) = pk(a[2], a[3]);
            } else if (MODE == 1) {
                __half* C = (__half*)Cv;
                __half2 g0 = *(const __half2*)(Gv + o0);
                __half2 g1 = *(const __half2*)(Gv + o1);
                float2 f0 = __half22float2(g0);
                float2 f1 = __half22float2(g1);
                *(uint32_t*)(C + o0) = pk(silu_f(f0.x) * a[0], silu_f(f0.y) * a[1]);
                *(uint32_t*)(C + o1) = pk(silu_f(f1.x) * a[2], silu_f(f1.y) * a[3]);
            } else {
                float* C = (float*)Cv;
                *(float2*)(C + o0) = make_float2(a[0], a[1]);
                *(float2*)(C + o1) = make_float2(a[2], a[3]);
            }
        }
    }

    // ---- MODE 0 sideband: convert up_w + down_w while DRAM is idle ----
    if (MODE == 0) {
        const size_t nth = (size_t)gridDim.x * gridDim.y * 256;
        size_t gt = ((size_t)blockIdx.y * gridDim.x + blockIdx.x) * 256 + tid;
#pragma unroll 1
        for (size_t i = gt; i < (size_t)n4w; i += nth) {
            float4 v = wsrc0[i];
            uint2 o;
            o.x = pk(v.x, v.y);
            o.y = pk(v.z, v.w);
            wdst0[i] = o;
            float4 u = wsrc1[i];
            uint2 p;
            p.x = pk(u.x, u.y);
            p.y = pk(u.z, u.w);
            wdst1[i] = p;
        }
    }
}

// ---------------- host launcher -------------------------------------------------
extern "C" void kernel_launch(void* const* d_in, const int* in_sizes, int n_in,
                              void* d_out, int out_size) {
    const float* x  = (const float*)d_in[0];
    const float* gw = (const float*)d_in[1];
    const float* uw = (const float*)d_in[2];
    const float* dw = (const float*)d_in[3];
    const int*   gs = (const int*)d_in[4];
    float* out = (float*)d_out;

    // Resolve REAL device addresses of __device__ scratch (host shadow trap).
    void *p_xh = nullptr, *p_gate = nullptr, *p_hid = nullptr, *p_wh = nullptr;
    cudaGetSymbolAddress(&p_xh, g_xh);
    cudaGetSymbolAddress(&p_gate, g_gate);
    cudaGetSymbolAddress(&p_hid, g_hid);
    cudaGetSymbolAddress(&p_wh, g_wh);
    __half* xh   = (__half*)p_xh;
    __half* gate = (__half*)p_gate;
    __half* hid  = (__half*)p_hid;
    __half* wh_g = (__half*)p_wh;
    __half* wh_u = wh_g + (size_t)NE * HD * ID;
    __half* wh_d = wh_u + (size_t)NE * HD * ID;

    cudaFuncSetAttribute(gemm_moe<HD, ID, 0>,
                         cudaFuncAttributeMaxDynamicSharedMemorySize, SMEM_DYN);
    cudaFuncSetAttribute(gemm_moe<HD, ID, 1>,
                         cudaFuncAttributeMaxDynamicSharedMemorySize, SMEM_DYN);
    cudaFuncSetAttribute(gemm_moe<ID, HD, 2>,
                         cudaFuncAttributeMaxDynamicSharedMemorySize, SMEM_DYN);

    // Phase 0: convert x + gate_w only (critical path); up_w/down_w are
    // converted inside the gate GEMM's sideband.
    const int nx4 = (TT * HD) / 4;            // 16.78M
    const int nw4 = (NE * HD * ID) / 4;       // 12.58M
    cvt_xgw<<<dim3((nx4 + 255) / 256, 1, 2), 256>>>(
        (const float4*)x, (const float4*)gw, xh, wh_g, nx4, nw4);

    // gate = x @ gate_w  -> g_gate (fp16); sideband converts uw->wh_u, dw->wh_d
    gemm_moe<HD, ID, 0><<<dim3(ID / 128, TT / 128), 256, SMEM_DYN>>>(
        xh, wh_g, gate, nullptr, gs,
        (const float4*)uw, (const float4*)dw, (uint2*)wh_u, (uint2*)wh_d, nw4);
    // hid = silu(gate) * (x @ up_w) -> g_hid (fp16, fused epilogue)
    gemm_moe<HD, ID, 1><<<dim3(ID / 128, TT / 128), 256, SMEM_DYN>>>(
        xh, wh_u, hid, gate, gs, nullptr, nullptr, nullptr, nullptr, 0);
    // out = hid @ down_w            -> out (fp32)
    gemm_moe<ID, HD, 2><<<dim3(HD / 128, TT / 128), 256, SMEM_DYN>>>(
        hid, wh_d, out, nullptr, gs, nullptr, nullptr, nullptr, nullptr, 0);
}

// round 15
// speedup vs baseline: 1.4201x; 1.0044x over previous
#include <cuda_runtime.h>
#include <cuda_fp16.h>
#include <cstdint>
#include <cstddef>

#define NE 16
#define HD 2048
#define ID 1536
#define TT 32768

// ---------------- device scratch (allocation-free rule) -------------------------
__device__ __half g_xh[(size_t)TT * HD];                  // x fp16          (128MB)
__device__ __half g_gate[(size_t)TT * ID];                // gate proj fp16  ( 96MB)
__device__ __half g_hid[(size_t)TT * ID];                 // silu(g)*up fp16 ( 96MB)
__device__ __half g_wh[(size_t)NE * 3 * HD * ID];         // fp16 weights    (302MB)
__device__ int    g_cnt[TT / 128];                        // per-mtile up counters

// ---------------- helpers -------------------------------------------------------
__device__ __forceinline__ uint32_t smem_u32(const void* p) {
    uint32_t a;
    asm("{ .reg .u64 t; cvta.to.shared.u64 t, %1; cvt.u32.u64 %0, t; }" : "=r"(a) : "l"(p));
    return a;
}
__device__ __forceinline__ void cp16(uint32_t dst, const void* src) {
    asm volatile("cp.async.cg.shared.global [%0], [%1], 16;" :: "r"(dst), "l"(src));
}
__device__ __forceinline__ void ldsm4(uint32_t& r0, uint32_t& r1, uint32_t& r2,
                                      uint32_t& r3, uint32_t a) {
    asm volatile("ldmatrix.sync.aligned.m8n8.x4.shared.b16 {%0,%1,%2,%3}, [%4];"
                 : "=r"(r0), "=r"(r1), "=r"(r2), "=r"(r3) : "r"(a));
}
__device__ __forceinline__ void ldsm4t(uint32_t& r0, uint32_t& r1, uint32_t& r2,
                                       uint32_t& r3, uint32_t a) {
    asm volatile("ldmatrix.sync.aligned.m8n8.x4.trans.shared.b16 {%0,%1,%2,%3}, [%4];"
                 : "=r"(r0), "=r"(r1), "=r"(r2), "=r"(r3) : "r"(a));
}
__device__ __forceinline__ void mma16816(float* c, uint32_t a0, uint32_t a1, uint32_t a2,
                                         uint32_t a3, uint32_t b0, uint32_t b1) {
    asm volatile(
        "mma.sync.aligned.m16n8k16.row.col.f32.f16.f16.f32 "
        "{%0,%1,%2,%3}, {%4,%5,%6,%7}, {%8,%9}, {%0,%1,%2,%3};"
        : "+f"(c[0]), "+f"(c[1]), "+f"(c[2]), "+f"(c[3])
        : "r"(a0), "r"(a1), "r"(a2), "r"(a3), "r"(b0), "r"(b1));
}
__device__ __forceinline__ uint32_t pk(float a, float b) {
    __half2 h = __floats2half2_rn(a, b);
    return *reinterpret_cast<uint32_t*>(&h);
}
__device__ __forceinline__ float silu_f(float x) { return x / (1.0f + __expf(-x)); }

// ---------------- fp32 -> fp16 conversion (x + gate_w) + flag reset --------------
__global__ void cvt_xgw(const float4* __restrict__ x, const float4* __restrict__ gw,
                        __half* __restrict__ xd, __half* __restrict__ gd,
                        int n4x, int n4w) {
    int i = blockIdx.x * blockDim.x + threadIdx.x;
    if (blockIdx.z == 1 && blockIdx.x == 0) g_cnt[threadIdx.x] = 0;  // 256 counters
    const float4* src;
    __half* dst;
    int n;
    if (blockIdx.z == 0) { src = x;  dst = xd; n = n4x; }
    else                 { src = gw; dst = gd; n = n4w; }
    if (i < n) {
        float4 v = src[i];
        uint2 o;
        o.x = pk(v.x, v.y);
        o.y = pk(v.z, v.w);
        *reinterpret_cast<uint2*>(dst + (size_t)i * 4) = o;
    }
}

// ---------------- GEMM body (R12/R14 proven core, as device template) ------------
// CTA tile 128x128, K-chunk 64, 256 threads (8 warps, 2x4 grid of 64x32 warp
// tiles), 3-stage cp.async pipeline, loads of chunk i+2 interleaved into the
// ks-steps of compute(i).
static constexpr int STG_A = 128 * 64 * 2;     // 16KB
static constexpr int STG_B = 64 * 128 * 2;     // 16KB
static constexpr int STG = STG_A + STG_B;      // 32KB
static constexpr int SMEM_DYN = 3 * STG + 128; // ~96KB

template <int KDIM, int NDIM, int MODE>
__device__ __forceinline__ void gemm_body(
    const __half* __restrict__ Ag, const __half* __restrict__ Ball,
    void* __restrict__ Cv, const __half* __restrict__ Gv,
    const int* s_cum, char* dsm, int m0, int n0, int tid) {

    int e = 0;
#pragma unroll
    for (int k = 1; k < NE; ++k) e += (s_cum[k] <= m0) ? 1 : 0;

    const __half* Bg = Ball + (size_t)e * KDIM * NDIM + n0;
    const __half* Ap = Ag + (size_t)m0 * KDIM;

    const uint32_t base = (smem_u32(dsm) + 127u) & ~127u;
    const int lane = tid & 31, wid = tid >> 5;
    const int wm = wid >> 2, wn = wid & 3;

    const int rA = tid >> 3, qA = tid & 7;
    const uint32_t oA0 = rA * 128 + ((qA ^ (rA & 7)) << 4);
    const __half* gAp = Ap + (size_t)rA * KDIM + qA * 8;
    const int rB = tid >> 4, cB = tid & 15;
    const uint32_t oB0 = rB * 256 + ((cB ^ (rB & 7)) << 4);
    const __half* gBp = Bg + (size_t)rB * NDIM + cB * 8;

    auto load_full = [&](int slot, int ch) {
        const uint32_t dA = base + slot * STG + oA0;
        const uint32_t dB = base + slot * STG + STG_A + oB0;
        const __half* sa = gAp + ch * 64;
        const __half* sb = gBp + (size_t)(ch * 64) * NDIM;
#pragma unroll
        for (int it = 0; it < 4; ++it)
            cp16(dA + it * 4096, sa + (size_t)(it * 32) * KDIM);
#pragma unroll
        for (int it = 0; it < 4; ++it)
            cp16(dB + it * 4096, sb + (size_t)(it * 16) * NDIM);
        asm volatile("cp.async.commit_group;" ::: "memory");
    };

    float acc[4][4][4];
#pragma unroll
    for (int a = 0; a < 4; ++a)
#pragma unroll
        for (int b = 0; b < 4; ++b)
#pragma unroll
            for (int c = 0; c < 4; ++c) acc[a][b][c] = 0.f;

    auto step = [&](int slot, int dst, int ch, bool doload) {
        const uint32_t Ab = base + slot * STG;
        const uint32_t Bb = Ab + STG_A;
        const uint32_t dA = base + dst * STG + oA0;
        const uint32_t dB = base + dst * STG + STG_A + oB0;
        const __half* sa = gAp + ch * 64;
        const __half* sb = gBp + (size_t)(ch * 64) * NDIM;
        const int sub = lane >> 3, lr = lane & 7;
#pragma unroll
        for (int ks = 0; ks < 4; ++ks) {
            uint32_t bfr[8];
#pragma unroll
            for (int np = 0; np < 2; ++np) {
                int krow = ks * 16 + (sub & 1) * 8 + lr;
                int ng = wn * 4 + np * 2 + (sub >> 1);
                uint32_t addr = Bb + krow * 256 + ((ng ^ (krow & 7)) << 4);
                ldsm4t(bfr[np * 4 + 0], bfr[np * 4 + 1], bfr[np * 4 + 2],
                       bfr[np * 4 + 3], addr);
            }
            if (doload) {
                cp16(dA + ks * 4096, sa + (size_t)(ks * 32) * KDIM);
                cp16(dB + ks * 4096, sb + (size_t)(ks * 16) * NDIM);
            }
#pragma unroll
            for (int mb = 0; mb < 4; ++mb) {
                int row = wm * 64 + mb * 16 + (sub & 1) * 8 + lr;
                int q = ks * 2 + (sub >> 1);
                uint32_t addr = Ab + row * 128 + ((q ^ (row & 7)) << 4);
                uint32_t a0, a1, a2, a3;
                ldsm4(a0, a1, a2, a3, addr);
#pragma unroll
                for (int np = 0; np < 2; ++np) {
                    mma16816(acc[mb][np * 2 + 0], a0, a1, a2, a3,
                             bfr[np * 4 + 0], bfr[np * 4 + 1]);
                    mma16816(acc[mb][np * 2 + 1], a0, a1, a2, a3,
                             bfr[np * 4 + 2], bfr[np * 4 + 3]);
                }
            }
        }
        if (doload) asm volatile("cp.async.commit_group;" ::: "memory");
    };

    const int nch = KDIM / 64;
    load_full(0, 0);
    load_full(1, 1);

#pragma unroll 1
    for (int i = 0; i < nch; ++i) {
        if (i + 1 < nch) asm volatile("cp.async.wait_group 1;" ::: "memory");
        else             asm volatile("cp.async.wait_group 0;" ::: "memory");
        __syncthreads();
        const bool dl = (i + 2 < nch);
        step(i % 3, (i + 2) % 3, dl ? (i + 2) : 0, dl);
    }

    const int r0 = m0 + wm * 64 + (lane >> 2);
    const int c0 = n0 + wn * 32 + (lane & 3) * 2;
#pragma unroll
    for (int mb = 0; mb < 4; ++mb) {
#pragma unroll
        for (int nb = 0; nb < 4; ++nb) {
            const int rr = r0 + mb * 16;
            const int cc = c0 + nb * 8;
            const size_t o0 = (size_t)rr * NDIM + cc;
            const size_t o1 = (size_t)(rr + 8) * NDIM + cc;
            float* a = acc[mb][nb];
            if (MODE == 0) {
                __half* C = (__half*)Cv;
                *(uint32_t*)(C + o0) = pk(a[0], a[1]);
                *(uint32_t*)(C + o1) = pk(a[2], a[3]);
            } else if (MODE == 1) {
                __half* C = (__half*)Cv;
                __half2 g0 = *(const __half2*)(Gv + o0);
                __half2 g1 = *(const __half2*)(Gv + o1);
                float2 f0 = __half22float2(g0);
                float2 f1 = __half22float2(g1);
                *(uint32_t*)(C + o0) = pk(silu_f(f0.x) * a[0], silu_f(f0.y) * a[1]);
                *(uint32_t*)(C + o1) = pk(silu_f(f1.x) * a[2], silu_f(f1.y) * a[3]);
            } else {
                float* C = (float*)Cv;
                *(float2*)(C + o0) = make_float2(a[0], a[1]);
                *(float2*)(C + o1) = make_float2(a[2], a[3]);
            }
        }
    }
}

// ---------------- kernel 1: gate GEMM + weight-conversion sideband ---------------
__global__ void __launch_bounds__(256, 2)
gemm_gate(const __half* __restrict__ Ag, const __half* __restrict__ Ball,
          __half* __restrict__ Cv, const int* __restrict__ gs,
          const float4* __restrict__ wsrc0, const float4* __restrict__ wsrc1,
          uint2* __restrict__ wdst0, uint2* __restrict__ wdst1, int n4w) {
    extern __shared__ char dsm[];
    __shared__ int s_cum[NE];
    const int tid = threadIdx.x;
    if (tid == 0) {
        int c = 0;
#pragma unroll
        for (int k = 0; k < NE; ++k) { s_cum[k] = c; c += gs[k]; }
    }
    __syncthreads();

    gemm_body<HD, ID, 0>(Ag, Ball, Cv, nullptr, s_cum, dsm,
                         blockIdx.y * 128, blockIdx.x * 128, tid);

    // sideband: convert up_w + down_w while GEMM leaves DRAM idle
    const size_t nth = (size_t)gridDim.x * gridDim.y * 256;
    size_t gt = ((size_t)blockIdx.y * gridDim.x + blockIdx.x) * 256 + tid;
#pragma unroll 1
    for (size_t i = gt; i < (size_t)n4w; i += nth) {
        float4 v = wsrc0[i];
        uint2 o;
        o.x = pk(v.x, v.y);
        o.y = pk(v.z, v.w);
        wdst0[i] = o;
        float4 u = wsrc1[i];
        uint2 p;
        p.x = pk(u.x, u.y);
        p.y = pk(u.z, u.w);
        wdst1[i] = p;
    }
}

// ---------------- kernel 2: fused up + down (one launch, counter-synced) ---------
// bids [0, 3072): up tiles (mt = bid/12, nt = bid%12) -> hid, then cnt[mt]++.
// bids [3072, 7168): down tiles; spin until cnt[mt]==12, then GEMM on hid.
static constexpr int UP_TILES = (TT / 128) * (ID / 128);   // 3072
static constexpr int DN_TILES = (TT / 128) * (HD / 128);   // 4096

__global__ void __launch_bounds__(256, 2)
gemm_updown(const __half* __restrict__ Xh, const __half* __restrict__ Uw,
            __half* __restrict__ Hid, const __half* __restrict__ Gate,
            const __half* __restrict__ Dw, float* __restrict__ Out,
            const int* __restrict__ gs) {
    extern __shared__ char dsm[];
    __shared__ int s_cum[NE];
    const int tid = threadIdx.x;
    if (tid == 0) {
        int c = 0;
#pragma unroll
        for (int k = 0; k < NE; ++k) { s_cum[k] = c; c += gs[k]; }
    }
    __syncthreads();

    const int bid = blockIdx.x;
    if (bid < UP_TILES) {
        const int mt = bid / (ID / 128), nt = bid % (ID / 128);
        gemm_body<HD, ID, 1>(Xh, Uw, Hid, Gate, s_cum, dsm,
                             mt * 128, nt * 128, tid);
        __threadfence();
        __syncthreads();
        if (tid == 0) atomicAdd(&g_cnt[mt], 1);
    } else {
        const int d = bid - UP_TILES;
        const int mt = d / (HD / 128), nt = d % (HD / 128);
        if (tid == 0) {
            while (*(volatile int*)&g_cnt[mt] < (ID / 128)) { }
        }
        __syncthreads();
        __threadfence();
        gemm_body<ID, HD, 2>(Hid, Dw, Out, nullptr, s_cum, dsm,
                             mt * 128, nt * 128, tid);
    }
}

// ---------------- host launcher -------------------------------------------------
extern "C" void kernel_launch(void* const* d_in, const int* in_sizes, int n_in,
                              void* d_out, int out_size) {
    const float* x  = (const float*)d_in[0];
    const float* gw = (const float*)d_in[1];
    const float* uw = (const float*)d_in[2];
    const float* dw = (const float*)d_in[3];
    const int*   gs = (const int*)d_in[4];
    float* out = (float*)d_out;

    // Resolve REAL device addresses of __device__ scratch (host shadow trap).
    void *p_xh = nullptr, *p_gate = nullptr, *p_hid = nullptr, *p_wh = nullptr;
    cudaGetSymbolAddress(&p_xh, g_xh);
    cudaGetSymbolAddress(&p_gate, g_gate);
    cudaGetSymbolAddress(&p_hid, g_hid);
    cudaGetSymbolAddress(&p_wh, g_wh);
    __half* xh   = (__half*)p_xh;
    __half* gate = (__half*)p_gate;
    __half* hid  = (__half*)p_hid;
    __half* wh_g = (__half*)p_wh;
    __half* wh_u = wh_g + (size_t)NE * HD * ID;
    __half* wh_d = wh_u + (size_t)NE * HD * ID;

    cudaFuncSetAttribute(gemm_gate,
                         cudaFuncAttributeMaxDynamicSharedMemorySize, SMEM_DYN);
    cudaFuncSetAttribute(gemm_updown,
                         cudaFuncAttributeMaxDynamicSharedMemorySize, SMEM_DYN);

    // Phase 0: convert x + gate_w (critical path), reset counters.
    const int nx4 = (TT * HD) / 4;
    const int nw4 = (NE * HD * ID) / 4;
    cvt_xgw<<<dim3((nx4 + 255) / 256, 1, 2), 256>>>(
        (const float4*)x, (const float4*)gw, xh, wh_g, nx4, nw4);

    // Phase 1: gate GEMM (sideband converts uw -> wh_u, dw -> wh_d).
    gemm_gate<<<dim3(ID / 128, TT / 128), 256, SMEM_DYN>>>(
        xh, wh_g, gate, gs,
        (const float4*)uw, (const float4*)dw, (uint2*)wh_u, (uint2*)wh_d, nw4);

    // Phase 2: fused up + down (down backfills the up wave tail).
    gemm_updown<<<UP_TILES + DN_TILES, 256, SMEM_DYN>>>(
        xh, wh_u, hid, gate, wh_d, out, gs);
}